// round 14
// baseline (speedup 1.0000x reference)
#include <cuda_runtime.h>

#define BATCH 256
#define TT    512
#define NN    128

// 64 MiB state history + batch ordering (static __device__ = allocation-free).
__device__ __align__(16) float d_hist[(size_t)BATCH * TT * NN];
__device__ int d_order[BATCH];

// Rank-sort batches by length descending (unique ranks via index tie-break).
__global__ void sort_kernel(const int* __restrict__ lens) {
    int b = threadIdx.x;
    int L = lens[b];
    int r = 0;
    for (int k = 0; k < BATCH; ++k) {
        int Lk = lens[k];
        r += (Lk > L) || (Lk == L && k < b);
    }
    d_order[r] = b;
}

// Order-preserving f32 -> u32 map (finite inputs).
__device__ __forceinline__ unsigned ordf(float f) {
    int b = __float_as_int(f);
    return (unsigned)(b ^ ((b >> 31) | 0x80000000));
}

__global__ __launch_bounds__(256)
void viterbi_kernel(const float* __restrict__ logits,
                    const float* __restrict__ trans,
                    const int*   __restrict__ lens,
                    float*       __restrict__ out) {   // output dtype: float32
    extern __shared__ float smem[];
    float* transT = smem;              // [NN][NN]: transT[j*NN+i] = T[i][j] (64KB)
    float* sb     = transT + NN * NN;  // [2][NN] ping-pong state

    const int tid  = threadIdx.x;
    const int j    = tid >> 1;         // tag owned by this thread pair
    const int h    = tid & 1;          // half of i-range: [64h, 64h+64)
    const int lane = tid & 31;

    // Length-balanced pairing: rank m with rank 255-m (bijective over 0..255).
    const int bk   = blockIdx.x;
    const int rank = (bk < 148) ? bk : (403 - bk);
    const int b    = d_order[rank];

    int L = __ldg(lens + b);
    L = max(1, min(L, TT));            // defensive clamp (no-op on valid data)

    const float* xb    = logits + (size_t)b * TT * NN;
    float*       hb    = d_hist + (size_t)b * TT * NN;
    const size_t obase = (size_t)b * TT;

    // Fill transposed transitions in smem (one-time).
    for (int k = tid; k < NN * NN; k += 256) {
        int i = k >> 7, jj = k & 127;
        transT[jj * NN + i] = __ldg(trans + k);
    }

    // Per-thread packed transition registers:
    // trp[r] = pack( T[64h+2r][j], T[64h+2r+1][j] )  -> 32 x b64.
    unsigned long long trp[32];
    #pragma unroll
    for (int r = 0; r < 32; ++r) {
        float lo = __ldg(trans + (size_t)(64 * h + 2 * r)     * NN + j);
        float hi = __ldg(trans + (size_t)(64 * h + 2 * r + 1) * NN + j);
        asm("mov.b64 %0, {%1, %2};" : "=l"(trp[r]) : "f"(lo), "f"(hi));
    }

    // init: state0 = logits[b,0,:]; zero output row (mask for t >= L).
    if (h == 0) {
        float v = __ldg(xb + j);
        sb[j] = v;
        hb[j] = v;
    }
    out[obase + tid]       = 0.0f;
    out[obase + tid + 256] = 0.0f;
    __syncthreads();

    const float NEG_INF = __int_as_float(0xff800000);

    // ---------------- forward (values only, packed f32x2 adds) ----------------
    int pp = 0;
    float xcur = __ldg(xb + NN + j);                                   // x[1][j]
    for (int t = 1; t < L; ++t) {
        float xnext = __ldg(xb + (size_t)min(t + 1, TT - 1) * NN + j); // prefetch

        // State as b64 pairs: one LDS.128 -> two register pairs, no pack MOVs.
        const ulonglong2* s2 = (const ulonglong2*)(sb + pp * NN) + (h << 4);
        float m0 = NEG_INF, m1 = NEG_INF, m2 = NEG_INF, m3 = NEG_INF;
        #pragma unroll
        for (int g = 0; g < 16; ++g) {
            ulonglong2 sv = s2[g];                 // states 64h+4g .. 64h+4g+3
            unsigned long long p0, p1;
            asm("add.rn.f32x2 %0, %1, %2;" : "=l"(p0) : "l"(sv.x), "l"(trp[2 * g]));
            asm("add.rn.f32x2 %0, %1, %2;" : "=l"(p1) : "l"(sv.y), "l"(trp[2 * g + 1]));
            float f0, f1, f2, f3;
            asm("mov.b64 {%0, %1}, %2;" : "=f"(f0), "=f"(f1) : "l"(p0));
            asm("mov.b64 {%0, %1}, %2;" : "=f"(f2), "=f"(f3) : "l"(p1));
            m0 = fmaxf(m0, f0);
            m1 = fmaxf(m1, f1);
            m2 = fmaxf(m2, f2);
            m3 = fmaxf(m3, f3);
        }
        float mf = fmaxf(fmaxf(m0, m1), fmaxf(m2, m3));
        mf = fmaxf(mf, __shfl_xor_sync(0xffffffffu, mf, 1));

        if (h == 0) {
            float ns = mf + xcur;
            sb[(pp ^ 1) * NN + j] = ns;
            hb[(size_t)t * NN + j] = ns;
        }
        xcur = xnext;
        __syncthreads();
        pp ^= 1;
    }

    // ---------------- backtrace by single-column recompute (warp 0) ----------------
    // Recomputed sums state_{t-1}[i] + T[i][cur] are bitwise identical to the
    // forward pass, so first-index argmax reproduces the reference backpointers.
    if (tid < 32) {
        // last_tag = first-index argmax of final state.
        const float4 sv = ((const float4*)(sb + pp * NN))[lane];
        float lm = sv.x; int li = 0;
        if (sv.y > lm) { lm = sv.y; li = 1; }
        if (sv.z > lm) { lm = sv.z; li = 2; }
        if (sv.w > lm) { lm = sv.w; li = 3; }
        unsigned uu   = ordf(lm);
        unsigned Mg   = __reduce_max_sync(0xffffffffu, uu);
        unsigned cand = (uu == Mg) ? (unsigned)(4 * lane + li) : 0xffffffffu;
        int cur = (int)__reduce_min_sync(0xffffffffu, cand);
        if (lane == 0) out[obase + (L - 1)] = (float)cur;

        // Depth-2 prefetch of history rows (addresses independent of cur).
        float4 rA = ((const float4*)(hb + (size_t)max(L - 2, 0) * NN))[lane];
        float4 rB = ((const float4*)(hb + (size_t)max(L - 3, 0) * NN))[lane];

        for (int t = L - 1; t >= 1; --t) {
            float4 r = rA;                         // state_{t-1}
            rA = rB;
            rB = ((const float4*)(hb + (size_t)max(t - 3, 0) * NN))[lane];

            // T[:, cur] from smem transposed copy: only cur-dependent access is LDS.
            const float4 tv = ((const float4*)(transT + cur * NN))[lane];
            float v0 = r.x + tv.x, v1 = r.y + tv.y;
            float v2 = r.z + tv.z, v3 = r.w + tv.w;
            float lm2 = v0; int li2 = 0;
            if (v1 > lm2) { lm2 = v1; li2 = 1; }
            if (v2 > lm2) { lm2 = v2; li2 = 2; }
            if (v3 > lm2) { lm2 = v3; li2 = 3; }
            unsigned u2 = ordf(lm2);
            unsigned M2 = __reduce_max_sync(0xffffffffu, u2);
            unsigned c2 = (u2 == M2) ? (unsigned)(4 * lane + li2) : 0xffffffffu;
            cur = (int)__reduce_min_sync(0xffffffffu, c2);
            if (lane == 0) out[obase + (t - 1)] = (float)cur;
        }
    }
}

extern "C" void kernel_launch(void* const* d_in, const int* in_sizes, int n_in,
                              void* d_out, int out_size) {
    const float* logits = (const float*)d_in[0];
    const float* trans  = (const float*)((n_in > 1) ? d_in[1] : d_in[0]);
    const int*   lens   = (const int*)((n_in > 2) ? d_in[2] : d_in[0]);
    for (int i = 0; i < n_in; ++i) {
        int s = in_sizes[i];
        if      (s == BATCH * TT * NN) logits = (const float*)d_in[i];
        else if (s == NN * NN)         trans  = (const float*)d_in[i];
        else if (s == BATCH)           lens   = (const int*)d_in[i];
    }
    float* out = (float*)d_out;
    (void)out_size;

    const int smem_bytes = (NN * NN + 2 * NN) * (int)sizeof(float);  // 65.5 KB
    cudaFuncSetAttribute(viterbi_kernel,
                         cudaFuncAttributeMaxDynamicSharedMemorySize, smem_bytes);

    sort_kernel<<<1, BATCH>>>(lens);
    viterbi_kernel<<<BATCH, 256, smem_bytes>>>(logits, trans, lens, out);
}

// round 15
// speedup vs baseline: 1.0868x; 1.0868x over previous
#include <cuda_runtime.h>

#define BATCH 256
#define TT    512
#define NN    128

// 64 MiB state history + batch ordering (static __device__ = allocation-free).
__device__ __align__(16) float d_hist[(size_t)BATCH * TT * NN];
__device__ int d_order[BATCH];

// Rank-sort batches by length descending (unique ranks via index tie-break).
__global__ void sort_kernel(const int* __restrict__ lens) {
    int b = threadIdx.x;
    int L = lens[b];
    int r = 0;
    for (int k = 0; k < BATCH; ++k) {
        int Lk = lens[k];
        r += (Lk > L) || (Lk == L && k < b);
    }
    d_order[r] = b;
}

// Order-preserving f32 -> u32 map (finite inputs).
__device__ __forceinline__ unsigned ordf(float f) {
    int b = __float_as_int(f);
    return (unsigned)(b ^ ((b >> 31) | 0x80000000));
}

__global__ __launch_bounds__(128)
void viterbi_kernel(const float* __restrict__ logits,
                    const float* __restrict__ trans,
                    const int*   __restrict__ lens,
                    float*       __restrict__ out) {   // output dtype: float32
    extern __shared__ float smem[];
    float* transT = smem;              // [NN][NN]: transT[j*NN+i] = T[i][j] (64KB)
    float* sb     = transT + NN * NN;  // [2][NN] ping-pong state

    const int tid  = threadIdx.x;     // 0..127: this thread owns tag j = tid
    const int j    = tid;
    const int lane = tid & 31;

    // Length-balanced pairing: rank m with rank 255-m (bijective over 0..255).
    const int bk   = blockIdx.x;
    const int rank = (bk < 148) ? bk : (403 - bk);
    const int b    = d_order[rank];

    int L = __ldg(lens + b);
    L = max(1, min(L, TT));            // defensive clamp (no-op on valid data)

    const float* xb    = logits + (size_t)b * TT * NN;
    float*       hb    = d_hist + (size_t)b * TT * NN;
    const size_t obase = (size_t)b * TT;

    // Fill transposed transitions in smem (one-time, coalesced LDG / linear STS).
    for (int k = tid; k < NN * NN; k += 128) {
        int i = k >> 7, jj = k & 127;
        transT[jj * NN + i] = __ldg(trans + k);
    }

    // Full transition column in registers: tr[i] = T[i][j].
    float tr[NN];
    #pragma unroll
    for (int i = 0; i < NN; ++i)
        tr[i] = __ldg(trans + (size_t)i * NN + j);

    // init: state0 = logits[b,0,:]; zero output row (mask for t >= L).
    {
        float v = __ldg(xb + j);
        sb[j] = v;
        hb[j] = v;
    }
    out[obase + tid]        = 0.0f;
    out[obase + tid + 128]  = 0.0f;
    out[obase + tid + 256]  = 0.0f;
    out[obase + tid + 384]  = 0.0f;
    __syncthreads();

    const float NEG_INF = __int_as_float(0xff800000);

    // ---------------- forward (values only) + history store ----------------
    int pp = 0;
    float xcur = __ldg(xb + (size_t)min(1, TT - 1) * NN + j);   // x[1][j]
    float xn1  = __ldg(xb + (size_t)min(2, TT - 1) * NN + j);   // x[2][j]
    for (int t = 1; t < L; ++t) {
        float xn2 = __ldg(xb + (size_t)min(t + 2, TT - 1) * NN + j); // dist-2 prefetch

        const float4* s4 = (const float4*)(sb + pp * NN);       // broadcast reads
        float a0 = NEG_INF, a1 = NEG_INF, a2 = NEG_INF, a3 = NEG_INF;
        float a4 = NEG_INF, a5 = NEG_INF, a6 = NEG_INF, a7 = NEG_INF;
        #pragma unroll
        for (int g = 0; g < 32; g += 2) {
            float4 s0 = s4[g];
            float4 s1 = s4[g + 1];
            a0 = fmaxf(a0, s0.x + tr[4 * g + 0]);
            a1 = fmaxf(a1, s0.y + tr[4 * g + 1]);
            a2 = fmaxf(a2, s0.z + tr[4 * g + 2]);
            a3 = fmaxf(a3, s0.w + tr[4 * g + 3]);
            a4 = fmaxf(a4, s1.x + tr[4 * g + 4]);
            a5 = fmaxf(a5, s1.y + tr[4 * g + 5]);
            a6 = fmaxf(a6, s1.z + tr[4 * g + 6]);
            a7 = fmaxf(a7, s1.w + tr[4 * g + 7]);
        }
        float m = fmaxf(fmaxf(fmaxf(a0, a1), fmaxf(a2, a3)),
                        fmaxf(fmaxf(a4, a5), fmaxf(a6, a7)));

        float ns = m + xcur;
        sb[(pp ^ 1) * NN + j]  = ns;
        hb[(size_t)t * NN + j] = ns;

        xcur = xn1;
        xn1  = xn2;
        __syncthreads();
        pp ^= 1;
    }

    // ---------------- backtrace by single-column recompute (warp 0) ----------------
    // Recomputed sums state_{t-1}[i] + T[i][cur] are bitwise identical to the
    // forward pass, so first-index argmax reproduces the reference backpointers.
    if (tid < 32) {
        // last_tag = first-index argmax of final state.
        const float4 sv = ((const float4*)(sb + pp * NN))[lane];
        float lm = sv.x; int li = 0;
        if (sv.y > lm) { lm = sv.y; li = 1; }
        if (sv.z > lm) { lm = sv.z; li = 2; }
        if (sv.w > lm) { lm = sv.w; li = 3; }
        unsigned uu   = ordf(lm);
        unsigned Mg   = __reduce_max_sync(0xffffffffu, uu);
        unsigned cand = (uu == Mg) ? (unsigned)(4 * lane + li) : 0xffffffffu;
        int cur = (int)__reduce_min_sync(0xffffffffu, cand);
        if (lane == 0) out[obase + (L - 1)] = (float)cur;

        // Depth-2 prefetch of history rows (addresses independent of cur).
        float4 rA = ((const float4*)(hb + (size_t)max(L - 2, 0) * NN))[lane];
        float4 rB = ((const float4*)(hb + (size_t)max(L - 3, 0) * NN))[lane];

        for (int t = L - 1; t >= 1; --t) {
            float4 r = rA;                         // state_{t-1}
            rA = rB;
            rB = ((const float4*)(hb + (size_t)max(t - 3, 0) * NN))[lane];

            // T[:, cur] from smem transposed copy: only cur-dependent access is LDS.
            const float4 tv = ((const float4*)(transT + cur * NN))[lane];
            float v0 = r.x + tv.x, v1 = r.y + tv.y;
            float v2 = r.z + tv.z, v3 = r.w + tv.w;
            float lm2 = v0; int li2 = 0;
            if (v1 > lm2) { lm2 = v1; li2 = 1; }
            if (v2 > lm2) { lm2 = v2; li2 = 2; }
            if (v3 > lm2) { lm2 = v3; li2 = 3; }
            unsigned u2 = ordf(lm2);
            unsigned M2 = __reduce_max_sync(0xffffffffu, u2);
            unsigned c2 = (u2 == M2) ? (unsigned)(4 * lane + li2) : 0xffffffffu;
            cur = (int)__reduce_min_sync(0xffffffffu, c2);
            if (lane == 0) out[obase + (t - 1)] = (float)cur;
        }
    }
}

extern "C" void kernel_launch(void* const* d_in, const int* in_sizes, int n_in,
                              void* d_out, int out_size) {
    const float* logits = (const float*)d_in[0];
    const float* trans  = (const float*)((n_in > 1) ? d_in[1] : d_in[0]);
    const int*   lens   = (const int*)((n_in > 2) ? d_in[2] : d_in[0]);
    for (int i = 0; i < n_in; ++i) {
        int s = in_sizes[i];
        if      (s == BATCH * TT * NN) logits = (const float*)d_in[i];
        else if (s == NN * NN)         trans  = (const float*)d_in[i];
        else if (s == BATCH)           lens   = (const int*)d_in[i];
    }
    float* out = (float*)d_out;
    (void)out_size;

    const int smem_bytes = (NN * NN + 2 * NN) * (int)sizeof(float);  // 65.5 KB
    cudaFuncSetAttribute(viterbi_kernel,
                         cudaFuncAttributeMaxDynamicSharedMemorySize, smem_bytes);

    sort_kernel<<<1, BATCH>>>(lens);
    viterbi_kernel<<<BATCH, 128, smem_bytes>>>(logits, trans, lens, out);
}